// round 2
// baseline (speedup 1.0000x reference)
#include <cuda_runtime.h>

// Problem constants
#define B_      256
#define L_      2048
#define V_      8
#define NS_     5        // shapelets
#define BAG_    409
#define SHIFT_  204
#define NB_     9        // windows
#define FEAT_   80       // 2*NS*V
#define NCLASS_ 10
#define BN_EPS_ 1e-5f

// Scratch
__device__ float g_feat[B_ * FEAT_];
__device__ float g_scale[FEAT_];
__device__ float g_shift[FEAT_];

// ---------------------------------------------------------------------------
// Kernel 1: per-(b,v) warp computes 5x9 L2 distances via the expansion
//   ||x - s||^2 = sum(x^2) + sum(s^2) - 2*sum(x*s)
// then min/mean over the 9 windows -> feat[b, :].
// ---------------------------------------------------------------------------
__global__ __launch_bounds__(256, 2)
void shapelet_feat_kernel(const float* __restrict__ x,
                          const float* __restrict__ shp,
                          float* __restrict__ feat)
{
    const int warp = threadIdx.x >> 5;
    const int lane = threadIdx.x & 31;
    const int g = blockIdx.x * 8 + warp;          // global warp id in [0, 2048)
    const int b = g >> 3;
    const int v = g & 7;

    const float* __restrict__ xr = x + (size_t)b * (V_ * L_) + (size_t)v * L_;
    const float* __restrict__ sv_base = shp + (size_t)v * BAG_;

    float c[NS_][NB_];
    float sx2[NB_];
    float ss2[NS_];
#pragma unroll
    for (int s = 0; s < NS_; s++) {
        ss2[s] = 0.f;
#pragma unroll
        for (int nb = 0; nb < NB_; nb++) c[s][nb] = 0.f;
    }
#pragma unroll
    for (int nb = 0; nb < NB_; nb++) sx2[nb] = 0.f;

    // 409 = 12*32 + 25
    for (int k = 0; k < 13; k++) {
        const int t = lane + (k << 5);
        const bool ok = (t < BAG_);

        float xv[NB_];
#pragma unroll
        for (int nb = 0; nb < NB_; nb++)
            xv[nb] = ok ? xr[nb * SHIFT_ + t] : 0.f;

        float sw[NS_];
#pragma unroll
        for (int s = 0; s < NS_; s++)
            sw[s] = ok ? sv_base[s * (V_ * BAG_) + t] : 0.f;

#pragma unroll
        for (int nb = 0; nb < NB_; nb++)
            sx2[nb] = fmaf(xv[nb], xv[nb], sx2[nb]);
#pragma unroll
        for (int s = 0; s < NS_; s++)
            ss2[s] = fmaf(sw[s], sw[s], ss2[s]);
#pragma unroll
        for (int s = 0; s < NS_; s++)
#pragma unroll
            for (int nb = 0; nb < NB_; nb++)
                c[s][nb] = fmaf(xv[nb], sw[s], c[s][nb]);
    }

    // Butterfly reduce all 59 accumulators across the warp (result in ALL lanes)
#pragma unroll
    for (int off = 16; off > 0; off >>= 1) {
#pragma unroll
        for (int nb = 0; nb < NB_; nb++)
            sx2[nb] += __shfl_xor_sync(0xffffffffu, sx2[nb], off);
#pragma unroll
        for (int s = 0; s < NS_; s++)
            ss2[s] += __shfl_xor_sync(0xffffffffu, ss2[s], off);
#pragma unroll
        for (int s = 0; s < NS_; s++)
#pragma unroll
            for (int nb = 0; nb < NB_; nb++)
                c[s][nb] += __shfl_xor_sync(0xffffffffu, c[s][nb], off);
    }

    // Epilogue distributed: lane s handles shapelet s
    if (lane < NS_) {
        const int s = lane;
        float dmin = 3.402823466e+38f;
        float dsum = 0.f;
#pragma unroll
        for (int nb = 0; nb < NB_; nb++) {
            float sx2v = __shfl_sync(0xffffffffu, sx2[nb], 0); // all lanes equal; keep uniform
            float d2 = sx2v + ss2[s] - 2.f * c[s][nb];
            float d = sqrtf(fmaxf(d2, 0.f));
            dmin = fminf(dmin, d);
            dsum += d;
        }
        float* fout = feat + (size_t)b * FEAT_;
        fout[s * V_ + v]            = dmin;
        fout[NS_ * V_ + s * V_ + v] = dsum * (1.f / 9.f);
    }
}

// ---------------------------------------------------------------------------
// Kernel 2a: BN batch stats (two-pass). One block per feature, one thread per
// batch row. Writes scale[f] = gamma*rstd, shift[f] = beta - mu*scale.
// ---------------------------------------------------------------------------
__global__ __launch_bounds__(256, 8)
void bn_stats_kernel(const float* __restrict__ feat,
                     const float* __restrict__ gamma,
                     const float* __restrict__ beta,
                     float* __restrict__ scale,
                     float* __restrict__ shift)
{
    const int f = blockIdx.x;
    const int tid = threadIdx.x;
    __shared__ float ws[8];
    __shared__ float wq[8];

    const float v = feat[tid * FEAT_ + f];

    float s = v;
#pragma unroll
    for (int o = 16; o > 0; o >>= 1) s += __shfl_xor_sync(0xffffffffu, s, o);
    if ((tid & 31) == 0) ws[tid >> 5] = s;
    __syncthreads();

    const float mu = (ws[0] + ws[1] + ws[2] + ws[3] +
                      ws[4] + ws[5] + ws[6] + ws[7]) * (1.f / 256.f);

    const float d = v - mu;
    float q = d * d;
#pragma unroll
    for (int o = 16; o > 0; o >>= 1) q += __shfl_xor_sync(0xffffffffu, q, o);
    if ((tid & 31) == 0) wq[tid >> 5] = q;
    __syncthreads();

    if (tid == 0) {
        const float var = (wq[0] + wq[1] + wq[2] + wq[3] +
                           wq[4] + wq[5] + wq[6] + wq[7]) * (1.f / 256.f);
        const float rstd = rsqrtf(var + BN_EPS_);
        const float sc = gamma[f] * rstd;
        scale[f] = sc;
        shift[f] = beta[f] - mu * sc;
    }
}

// ---------------------------------------------------------------------------
// Kernel 2b: FC with BN folded. One block per class, one thread per batch row.
// ---------------------------------------------------------------------------
__global__ __launch_bounds__(256, 8)
void fc_kernel(const float* __restrict__ feat,
               const float* __restrict__ scale,
               const float* __restrict__ shift,
               const float* __restrict__ w,
               const float* __restrict__ fb,
               float* __restrict__ out)
{
    const int c = blockIdx.x;
    const int b = threadIdx.x;
    __shared__ float wp[FEAT_];
    __shared__ float cbias;

    if (b < FEAT_)
        wp[b] = w[c * FEAT_ + b] * scale[b];

    if (b >= 128 && b < 160) {
        // warp 4 computes the folded bias: fb[c] + sum_f shift[f]*w[c,f]
        const int lane = b - 128;
        float a = 0.f;
        for (int f = lane; f < FEAT_; f += 32)
            a = fmaf(shift[f], w[c * FEAT_ + f], a);
#pragma unroll
        for (int o = 16; o > 0; o >>= 1) a += __shfl_xor_sync(0xffffffffu, a, o);
        if (lane == 0) cbias = a + fb[c];
    }
    __syncthreads();

    const float4* __restrict__ fr = (const float4*)(feat + b * FEAT_);
    float acc = cbias;
#pragma unroll
    for (int i = 0; i < FEAT_ / 4; i++) {
        float4 xv = fr[i];
        acc = fmaf(xv.x, wp[4 * i + 0], acc);
        acc = fmaf(xv.y, wp[4 * i + 1], acc);
        acc = fmaf(xv.z, wp[4 * i + 2], acc);
        acc = fmaf(xv.w, wp[4 * i + 3], acc);
    }
    out[b * NCLASS_ + c] = acc;
}

// ---------------------------------------------------------------------------
extern "C" void kernel_launch(void* const* d_in, const int* in_sizes, int n_in,
                              void* d_out, int out_size)
{
    const float* x     = (const float*)d_in[0];  // [256, 2048, 8]
    const float* shp   = (const float*)d_in[1];  // [1, 5, 8, 409, 1]
    const float* gamma = (const float*)d_in[2];  // [80]
    const float* beta  = (const float*)d_in[3];  // [80]
    const float* fcw   = (const float*)d_in[4];  // [10, 80]
    const float* fcb   = (const float*)d_in[5];  // [10]
    float* out = (float*)d_out;                  // [256, 10]

    float *feat = nullptr, *scale = nullptr, *shift = nullptr;
    cudaGetSymbolAddress((void**)&feat,  g_feat);
    cudaGetSymbolAddress((void**)&scale, g_scale);
    cudaGetSymbolAddress((void**)&shift, g_shift);

    shapelet_feat_kernel<<<256, 256>>>(x, shp, feat);
    bn_stats_kernel<<<FEAT_, 256>>>(feat, gamma, beta, scale, shift);
    fc_kernel<<<NCLASS_, 256>>>(feat, scale, shift, fcw, fcb, out);
}

// round 3
// speedup vs baseline: 1.1232x; 1.1232x over previous
#include <cuda_runtime.h>

// Problem constants
#define B_      256
#define L_      2048
#define V_      8
#define NS_     5        // shapelets
#define BAG_    409
#define BAGP_   416      // padded (zero-filled) shapelet length in smem
#define SHIFT_  204
#define NB_     9        // windows
#define FEAT_   80       // 2*NS*V
#define NCLASS_ 10
#define BN_EPS_ 1e-5f
#define NACC_   (NB_ + NS_ * NB_)   // 9 sx2 + 45 cross = 54

// Scratch
__device__ float g_feat[B_ * FEAT_];
__device__ float g_scale[FEAT_];
__device__ float g_shift[FEAT_];

// ---------------------------------------------------------------------------
// Kernel 1: block = (4 batches, 1 v). 2 warps per (b,v) split the t-range.
// ||x - s||^2 = sum(x^2) + sum(s^2) - 2*sum(x*s); shapelets staged in smem.
// ---------------------------------------------------------------------------
__global__ __launch_bounds__(256)
void shapelet_feat_kernel(const float* __restrict__ x,
                          const float* __restrict__ shp,
                          float* __restrict__ feat)
{
    const int tid  = threadIdx.x;
    const int warp = tid >> 5;
    const int lane = tid & 31;
    const int b_local = warp >> 1;          // 0..3
    const int half    = warp & 1;           // t-range half
    const int v  = blockIdx.x & 7;
    const int b  = (blockIdx.x >> 3) * 4 + b_local;

    __shared__ float s_shp[NS_][BAGP_];     // zero-padded shapelet slice for v
    __shared__ float s_ss2[NS_];
    __shared__ float s_part[4][2][NACC_];   // [b_local][half][9 sx2 | 45 c]

    // Stage shapelets (zero-pad 409..415)
    for (int i = tid; i < NS_ * BAGP_; i += 256) {
        const int s = i / BAGP_;
        const int t = i - s * BAGP_;
        s_shp[s][t] = (t < BAG_) ? shp[s * (V_ * BAG_) + v * BAG_ + t] : 0.f;
    }
    __syncthreads();

    // ss2[s] = sum_t shp[s,v,t]^2 : warps 0..4, one shapelet each
    if (warp < NS_) {
        float q = 0.f;
        for (int t = lane; t < BAG_; t += 32) {
            const float sv = s_shp[warp][t];
            q = fmaf(sv, sv, q);
        }
#pragma unroll
        for (int o = 16; o > 0; o >>= 1) q += __shfl_xor_sync(0xffffffffu, q, o);
        if (lane == 0) s_ss2[warp] = q;
    }

    // Main accumulation: this warp covers t = 32*half + 64*k + lane
    const float* __restrict__ xr = x + (size_t)b * (V_ * L_) + (size_t)v * L_;

    float c[NS_][NB_];
    float sx2[NB_];
#pragma unroll
    for (int s = 0; s < NS_; s++)
#pragma unroll
        for (int nb = 0; nb < NB_; nb++) c[s][nb] = 0.f;
#pragma unroll
    for (int nb = 0; nb < NB_; nb++) sx2[nb] = 0.f;

    const int kmax = half ? 6 : 7;          // half1 max t = 383; half0 last iter masked
    for (int k = 0; k < kmax; k++) {
        const int t = 32 * half + 64 * k + lane;
        const bool ok = (t < BAG_);

        float xv[NB_];
#pragma unroll
        for (int nb = 0; nb < NB_; nb++)
            xv[nb] = ok ? xr[nb * SHIFT_ + t] : 0.f;

#pragma unroll
        for (int nb = 0; nb < NB_; nb++)
            sx2[nb] = fmaf(xv[nb], xv[nb], sx2[nb]);

#pragma unroll
        for (int s = 0; s < NS_; s++) {
            const float sw = s_shp[s][t];   // zero-padded -> no mask needed
#pragma unroll
            for (int nb = 0; nb < NB_; nb++)
                c[s][nb] = fmaf(xv[nb], sw, c[s][nb]);
        }
    }

    // Warp reduce (all lanes end with totals)
#pragma unroll
    for (int o = 16; o > 0; o >>= 1) {
#pragma unroll
        for (int nb = 0; nb < NB_; nb++)
            sx2[nb] += __shfl_xor_sync(0xffffffffu, sx2[nb], o);
#pragma unroll
        for (int s = 0; s < NS_; s++)
#pragma unroll
            for (int nb = 0; nb < NB_; nb++)
                c[s][nb] += __shfl_xor_sync(0xffffffffu, c[s][nb], o);
    }

    if (lane == 0) {
        float* p = s_part[b_local][half];
#pragma unroll
        for (int nb = 0; nb < NB_; nb++) p[nb] = sx2[nb];
#pragma unroll
        for (int s = 0; s < NS_; s++)
#pragma unroll
            for (int nb = 0; nb < NB_; nb++) p[NB_ + s * NB_ + nb] = c[s][nb];
    }
    __syncthreads();

    // Epilogue: half-0 warps, lanes 0..4 handle shapelet s = lane
    if (half == 0 && lane < NS_) {
        const int s = lane;
        const float* p0 = s_part[b_local][0];
        const float* p1 = s_part[b_local][1];
        const float ss2v = s_ss2[s];
        float dmin = 3.402823466e+38f;
        float dsum = 0.f;
#pragma unroll
        for (int nb = 0; nb < NB_; nb++) {
            const float sx2t = p0[nb] + p1[nb];
            const float ct   = p0[NB_ + s * NB_ + nb] + p1[NB_ + s * NB_ + nb];
            const float d2 = sx2t + ss2v - 2.f * ct;
            const float d  = sqrtf(fmaxf(d2, 0.f));
            dmin = fminf(dmin, d);
            dsum += d;
        }
        float* fout = feat + (size_t)b * FEAT_;
        fout[s * V_ + v]            = dmin;
        fout[NS_ * V_ + s * V_ + v] = dsum * (1.f / 9.f);
    }
}

// ---------------------------------------------------------------------------
// Kernel 2a: BN batch stats (two-pass). One block per feature, one thread per
// batch row. Writes scale[f] = gamma*rstd, shift[f] = beta - mu*scale.
// ---------------------------------------------------------------------------
__global__ __launch_bounds__(256, 8)
void bn_stats_kernel(const float* __restrict__ feat,
                     const float* __restrict__ gamma,
                     const float* __restrict__ beta,
                     float* __restrict__ scale,
                     float* __restrict__ shift)
{
    const int f = blockIdx.x;
    const int tid = threadIdx.x;
    __shared__ float ws[8];
    __shared__ float wq[8];

    const float v = feat[tid * FEAT_ + f];

    float s = v;
#pragma unroll
    for (int o = 16; o > 0; o >>= 1) s += __shfl_xor_sync(0xffffffffu, s, o);
    if ((tid & 31) == 0) ws[tid >> 5] = s;
    __syncthreads();

    const float mu = (ws[0] + ws[1] + ws[2] + ws[3] +
                      ws[4] + ws[5] + ws[6] + ws[7]) * (1.f / 256.f);

    const float d = v - mu;
    float q = d * d;
#pragma unroll
    for (int o = 16; o > 0; o >>= 1) q += __shfl_xor_sync(0xffffffffu, q, o);
    if ((tid & 31) == 0) wq[tid >> 5] = q;
    __syncthreads();

    if (tid == 0) {
        const float var = (wq[0] + wq[1] + wq[2] + wq[3] +
                           wq[4] + wq[5] + wq[6] + wq[7]) * (1.f / 256.f);
        const float rstd = rsqrtf(var + BN_EPS_);
        const float sc = gamma[f] * rstd;
        scale[f] = sc;
        shift[f] = beta[f] - mu * sc;
    }
}

// ---------------------------------------------------------------------------
// Kernel 2b: FC with BN folded. One block per class, one thread per batch row.
// ---------------------------------------------------------------------------
__global__ __launch_bounds__(256, 8)
void fc_kernel(const float* __restrict__ feat,
               const float* __restrict__ scale,
               const float* __restrict__ shift,
               const float* __restrict__ w,
               const float* __restrict__ fb,
               float* __restrict__ out)
{
    const int c = blockIdx.x;
    const int b = threadIdx.x;
    __shared__ float wp[FEAT_];
    __shared__ float cbias;

    if (b < FEAT_)
        wp[b] = w[c * FEAT_ + b] * scale[b];

    if (b >= 128 && b < 160) {
        // warp 4 computes the folded bias: fb[c] + sum_f shift[f]*w[c,f]
        const int lane = b - 128;
        float a = 0.f;
        for (int f = lane; f < FEAT_; f += 32)
            a = fmaf(shift[f], w[c * FEAT_ + f], a);
#pragma unroll
        for (int o = 16; o > 0; o >>= 1) a += __shfl_xor_sync(0xffffffffu, a, o);
        if (lane == 0) cbias = a + fb[c];
    }
    __syncthreads();

    const float4* __restrict__ fr = (const float4*)(feat + b * FEAT_);
    float acc = cbias;
#pragma unroll
    for (int i = 0; i < FEAT_ / 4; i++) {
        float4 xv = fr[i];
        acc = fmaf(xv.x, wp[4 * i + 0], acc);
        acc = fmaf(xv.y, wp[4 * i + 1], acc);
        acc = fmaf(xv.z, wp[4 * i + 2], acc);
        acc = fmaf(xv.w, wp[4 * i + 3], acc);
    }
    out[b * NCLASS_ + c] = acc;
}

// ---------------------------------------------------------------------------
extern "C" void kernel_launch(void* const* d_in, const int* in_sizes, int n_in,
                              void* d_out, int out_size)
{
    const float* x     = (const float*)d_in[0];  // [256, 2048, 8]
    const float* shp   = (const float*)d_in[1];  // [1, 5, 8, 409, 1]
    const float* gamma = (const float*)d_in[2];  // [80]
    const float* beta  = (const float*)d_in[3];  // [80]
    const float* fcw   = (const float*)d_in[4];  // [10, 80]
    const float* fcb   = (const float*)d_in[5];  // [10]
    float* out = (float*)d_out;                  // [256, 10]

    float *feat = nullptr, *scale = nullptr, *shift = nullptr;
    cudaGetSymbolAddress((void**)&feat,  g_feat);
    cudaGetSymbolAddress((void**)&scale, g_scale);
    cudaGetSymbolAddress((void**)&shift, g_shift);

    shapelet_feat_kernel<<<512, 256>>>(x, shp, feat);
    bn_stats_kernel<<<FEAT_, 256>>>(feat, gamma, beta, scale, shift);
    fc_kernel<<<NCLASS_, 256>>>(feat, scale, shift, fcw, fcb, out);
}

// round 4
// speedup vs baseline: 1.3574x; 1.2085x over previous
#include <cuda_runtime.h>

// Problem constants
#define B_      256
#define L_      2048
#define V_      8
#define NS_     5        // shapelets
#define BAG_    409
#define BAGP_   416      // padded (zero-filled) shapelet length in smem
#define SHIFT_  204
#define NB_     9        // windows
#define FEAT_   80       // 2*NS*V
#define NCLASS_ 10
#define BN_EPS_ 1e-5f

// Scratch
__device__ float g_feat[B_ * FEAT_];
__device__ float g_scale[FEAT_];
__device__ float g_shift[FEAT_];

// ---------------------------------------------------------------------------
// Kernel 1: block = (8 batches, 1 v), one warp per (b,v).
// t-dimension vectorized: 3 x float4 iterations (t<384) + scalar tail (25).
// ||x - s||^2 = sum(x^2) + sum(s^2) - 2*sum(x*s); shapelets staged in smem.
// ---------------------------------------------------------------------------
__global__ __launch_bounds__(256, 2)
void shapelet_feat_kernel(const float* __restrict__ x,
                          const float* __restrict__ shp,
                          float* __restrict__ feat)
{
    const int tid  = threadIdx.x;
    const int warp = tid >> 5;
    const int lane = tid & 31;
    const int v  = blockIdx.x & 7;
    const int b  = (blockIdx.x >> 3) * 8 + warp;

    __shared__ float s_shp[NS_][BAGP_];     // zero-padded shapelet slice for v
    __shared__ float s_ss2[NS_];

    // Stage shapelets (zero-pad 409..415)
    for (int i = tid; i < NS_ * BAGP_; i += 256) {
        const int s = i / BAGP_;
        const int t = i - s * BAGP_;
        s_shp[s][t] = (t < BAG_) ? shp[s * (V_ * BAG_) + v * BAG_ + t] : 0.f;
    }
    __syncthreads();

    // ss2[s] = sum_t shp[s,v,t]^2 : warps 0..4, one shapelet each
    if (warp < NS_) {
        float q = 0.f;
        for (int t = lane; t < BAG_; t += 32) {
            const float sv = s_shp[warp][t];
            q = fmaf(sv, sv, q);
        }
#pragma unroll
        for (int o = 16; o > 0; o >>= 1) q += __shfl_xor_sync(0xffffffffu, q, o);
        if (lane == 0) s_ss2[warp] = q;
    }

    // ---- main accumulation ----
    const float* __restrict__ xr = x + (size_t)b * (V_ * L_) + (size_t)v * L_;

    float c[NS_][NB_];
    float sx2[NB_];
#pragma unroll
    for (int s = 0; s < NS_; s++)
#pragma unroll
        for (int nb = 0; nb < NB_; nb++) c[s][nb] = 0.f;
#pragma unroll
    for (int nb = 0; nb < NB_; nb++) sx2[nb] = 0.f;

#pragma unroll
    for (int k = 0; k < 3; k++) {
        const int t0 = 128 * k + 4 * lane;

        float4 xv[NB_];
#pragma unroll
        for (int nb = 0; nb < NB_; nb++)
            xv[nb] = *(const float4*)(xr + nb * SHIFT_ + t0);

        float4 sw[NS_];
#pragma unroll
        for (int s = 0; s < NS_; s++)
            sw[s] = *(const float4*)(&s_shp[s][t0]);

#pragma unroll
        for (int nb = 0; nb < NB_; nb++) {
            sx2[nb] = fmaf(xv[nb].x, xv[nb].x, sx2[nb]);
            sx2[nb] = fmaf(xv[nb].y, xv[nb].y, sx2[nb]);
            sx2[nb] = fmaf(xv[nb].z, xv[nb].z, sx2[nb]);
            sx2[nb] = fmaf(xv[nb].w, xv[nb].w, sx2[nb]);
        }
#pragma unroll
        for (int s = 0; s < NS_; s++)
#pragma unroll
            for (int nb = 0; nb < NB_; nb++) {
                c[s][nb] = fmaf(xv[nb].x, sw[s].x, c[s][nb]);
                c[s][nb] = fmaf(xv[nb].y, sw[s].y, c[s][nb]);
                c[s][nb] = fmaf(xv[nb].z, sw[s].z, c[s][nb]);
                c[s][nb] = fmaf(xv[nb].w, sw[s].w, c[s][nb]);
            }
    }

    // scalar tail: t = 384 + lane, valid for lane < 25
    {
        const int t = 384 + lane;
        const bool ok = (lane < 25);
        float xs[NB_];
#pragma unroll
        for (int nb = 0; nb < NB_; nb++)
            xs[nb] = ok ? xr[nb * SHIFT_ + t] : 0.f;
#pragma unroll
        for (int nb = 0; nb < NB_; nb++)
            sx2[nb] = fmaf(xs[nb], xs[nb], sx2[nb]);
#pragma unroll
        for (int s = 0; s < NS_; s++) {
            const float sv = s_shp[s][t];   // zero-padded, xs masked
#pragma unroll
            for (int nb = 0; nb < NB_; nb++)
                c[s][nb] = fmaf(xs[nb], sv, c[s][nb]);
        }
    }

    // Warp reduce (all lanes end with totals)
#pragma unroll
    for (int o = 16; o > 0; o >>= 1) {
#pragma unroll
        for (int nb = 0; nb < NB_; nb++)
            sx2[nb] += __shfl_xor_sync(0xffffffffu, sx2[nb], o);
#pragma unroll
        for (int s = 0; s < NS_; s++)
#pragma unroll
            for (int nb = 0; nb < NB_; nb++)
                c[s][nb] += __shfl_xor_sync(0xffffffffu, c[s][nb], o);
    }

    __syncthreads();   // s_ss2 visible to all warps

    // Epilogue: lanes 0..4 handle shapelet s = lane (all values uniform per warp)
    if (lane < NS_) {
        const int s = lane;
        const float ss2v = s_ss2[s];
        float dmin = 3.402823466e+38f;
        float dsum = 0.f;
#pragma unroll
        for (int nb = 0; nb < NB_; nb++) {
            const float d2 = sx2[nb] + ss2v - 2.f * c[s][nb];
            const float d  = sqrtf(fmaxf(d2, 0.f));
            dmin = fminf(dmin, d);
            dsum += d;
        }
        float* fout = feat + (size_t)b * FEAT_;
        fout[s * V_ + v]            = dmin;
        fout[NS_ * V_ + s * V_ + v] = dsum * (1.f / 9.f);
    }
}

// ---------------------------------------------------------------------------
// Kernel 2a: BN batch stats (two-pass). One block per feature, one thread per
// batch row. Writes scale[f] = gamma*rstd, shift[f] = beta - mu*scale.
// ---------------------------------------------------------------------------
__global__ __launch_bounds__(256, 8)
void bn_stats_kernel(const float* __restrict__ feat,
                     const float* __restrict__ gamma,
                     const float* __restrict__ beta,
                     float* __restrict__ scale,
                     float* __restrict__ shift)
{
    const int f = blockIdx.x;
    const int tid = threadIdx.x;
    __shared__ float ws[8];
    __shared__ float wq[8];

    const float v = feat[tid * FEAT_ + f];

    float s = v;
#pragma unroll
    for (int o = 16; o > 0; o >>= 1) s += __shfl_xor_sync(0xffffffffu, s, o);
    if ((tid & 31) == 0) ws[tid >> 5] = s;
    __syncthreads();

    const float mu = (ws[0] + ws[1] + ws[2] + ws[3] +
                      ws[4] + ws[5] + ws[6] + ws[7]) * (1.f / 256.f);

    const float d = v - mu;
    float q = d * d;
#pragma unroll
    for (int o = 16; o > 0; o >>= 1) q += __shfl_xor_sync(0xffffffffu, q, o);
    if ((tid & 31) == 0) wq[tid >> 5] = q;
    __syncthreads();

    if (tid == 0) {
        const float var = (wq[0] + wq[1] + wq[2] + wq[3] +
                           wq[4] + wq[5] + wq[6] + wq[7]) * (1.f / 256.f);
        const float rstd = rsqrtf(var + BN_EPS_);
        const float sc = gamma[f] * rstd;
        scale[f] = sc;
        shift[f] = beta[f] - mu * sc;
    }
}

// ---------------------------------------------------------------------------
// Kernel 2b: FC with BN folded. One block per class, one thread per batch row.
// ---------------------------------------------------------------------------
__global__ __launch_bounds__(256, 8)
void fc_kernel(const float* __restrict__ feat,
               const float* __restrict__ scale,
               const float* __restrict__ shift,
               const float* __restrict__ w,
               const float* __restrict__ fb,
               float* __restrict__ out)
{
    const int c = blockIdx.x;
    const int b = threadIdx.x;
    __shared__ float wp[FEAT_];
    __shared__ float cbias;

    if (b < FEAT_)
        wp[b] = w[c * FEAT_ + b] * scale[b];

    if (b >= 128 && b < 160) {
        // warp 4 computes the folded bias: fb[c] + sum_f shift[f]*w[c,f]
        const int lane = b - 128;
        float a = 0.f;
        for (int f = lane; f < FEAT_; f += 32)
            a = fmaf(shift[f], w[c * FEAT_ + f], a);
#pragma unroll
        for (int o = 16; o > 0; o >>= 1) a += __shfl_xor_sync(0xffffffffu, a, o);
        if (lane == 0) cbias = a + fb[c];
    }
    __syncthreads();

    const float4* __restrict__ fr = (const float4*)(feat + b * FEAT_);
    float acc = cbias;
#pragma unroll
    for (int i = 0; i < FEAT_ / 4; i++) {
        float4 xv = fr[i];
        acc = fmaf(xv.x, wp[4 * i + 0], acc);
        acc = fmaf(xv.y, wp[4 * i + 1], acc);
        acc = fmaf(xv.z, wp[4 * i + 2], acc);
        acc = fmaf(xv.w, wp[4 * i + 3], acc);
    }
    out[b * NCLASS_ + c] = acc;
}

// ---------------------------------------------------------------------------
extern "C" void kernel_launch(void* const* d_in, const int* in_sizes, int n_in,
                              void* d_out, int out_size)
{
    const float* x     = (const float*)d_in[0];  // [256, 2048, 8]
    const float* shp   = (const float*)d_in[1];  // [1, 5, 8, 409, 1]
    const float* gamma = (const float*)d_in[2];  // [80]
    const float* beta  = (const float*)d_in[3];  // [80]
    const float* fcw   = (const float*)d_in[4];  // [10, 80]
    const float* fcb   = (const float*)d_in[5];  // [10]
    float* out = (float*)d_out;                  // [256, 10]

    float *feat = nullptr, *scale = nullptr, *shift = nullptr;
    cudaGetSymbolAddress((void**)&feat,  g_feat);
    cudaGetSymbolAddress((void**)&scale, g_scale);
    cudaGetSymbolAddress((void**)&shift, g_shift);

    shapelet_feat_kernel<<<256, 256>>>(x, shp, feat);
    bn_stats_kernel<<<FEAT_, 256>>>(feat, gamma, beta, scale, shift);
    fc_kernel<<<NCLASS_, 256>>>(feat, scale, shift, fcw, fcb, out);
}